// round 15
// baseline (speedup 1.0000x reference)
#include <cuda_runtime.h>
#include <cuda_bf16.h>
#include <cuda_fp16.h>
#include <cstdint>

#define BB 128
#define TT 256
#define TPAST 256
#define TFULL 512
#define NH 4
#define DH 32
#define DM 128

#define OUT_K_OFF  4194304
#define OUT_V_OFF 12582912

__device__ float g_q [BB*NH*TT*DH];   // (B,H,T,Dh)
__device__ float g_ao[BB*TT*DM];      // (B,T,D) pre-proj

// Pre-split weights in GEMM-B smem layout: [mode][phase(4)][8KB]
__device__ char g_wqh[3 * 32768];
__device__ char g_wql[3 * 32768];
__device__ char g_wph[32768];
__device__ char g_wpl[32768];

// GEMM dynamic smem layout (M=64 tiles, 128 threads)
#define SM_AF32 0          // 2 x 8KB fp32 A staging (double buffer)
#define SM_ASP  16384      // 8KB split A tiles (hi 4K + lo 4K)
#define SM_B    24576      // 2 x 16KB split B (double buffer)
#define GEMM_SMEM 57344

// ---- baseline tensor-core helpers (sm_80+ features; OK for sm_103) ---------
__device__ __forceinline__ uint32_t smem_u32(const void* p) {
    uint32_t a;
    asm("{ .reg .u64 t; cvta.to.shared.u64 t, %1; cvt.u32.u64 %0, t; }" : "=r"(a) : "l"(p));
    return a;
}
__device__ __forceinline__ void ldsm_x4(uint32_t r[4], uint32_t addr) {
    asm volatile("ldmatrix.sync.aligned.m8n8.x4.shared.b16 {%0,%1,%2,%3}, [%4];"
        : "=r"(r[0]), "=r"(r[1]), "=r"(r[2]), "=r"(r[3]) : "r"(addr));
}
__device__ __forceinline__ void ldsm_x4_t(uint32_t r[4], uint32_t addr) {
    asm volatile("ldmatrix.sync.aligned.m8n8.x4.trans.shared.b16 {%0,%1,%2,%3}, [%4];"
        : "=r"(r[0]), "=r"(r[1]), "=r"(r[2]), "=r"(r[3]) : "r"(addr));
}
__device__ __forceinline__ void mma16816(float c[4], const uint32_t a[4],
                                         uint32_t b0, uint32_t b1) {
    asm volatile(
        "mma.sync.aligned.m16n8k16.row.col.f32.bf16.bf16.f32 "
        "{%0,%1,%2,%3}, {%4,%5,%6,%7}, {%8,%9}, {%0,%1,%2,%3};"
        : "+f"(c[0]), "+f"(c[1]), "+f"(c[2]), "+f"(c[3])
        : "r"(a[0]), "r"(a[1]), "r"(a[2]), "r"(a[3]), "r"(b0), "r"(b1));
}
__device__ __forceinline__ void mma16816_f16(float c[4], const uint32_t a[4],
                                             uint32_t b0, uint32_t b1) {
    asm volatile(
        "mma.sync.aligned.m16n8k16.row.col.f32.f16.f16.f32 "
        "{%0,%1,%2,%3}, {%4,%5,%6,%7}, {%8,%9}, {%0,%1,%2,%3};"
        : "+f"(c[0]), "+f"(c[1]), "+f"(c[2]), "+f"(c[3])
        : "r"(a[0]), "r"(a[1]), "r"(a[2]), "r"(a[3]), "r"(b0), "r"(b1));
}
__device__ __forceinline__ void cp16(uint32_t saddr, const void* g) {
    asm volatile("cp.async.cg.shared.global [%0], [%1], 16;"
                 :: "r"(saddr), "l"(g) : "memory");
}

// Split a float4 into hi/lo bf16x4 (8B each)
__device__ __forceinline__ void split4(const float4& v, uint2& uh, uint2& ul) {
    __nv_bfloat162 h01 = __floats2bfloat162_rn(v.x, v.y);
    __nv_bfloat162 h23 = __floats2bfloat162_rn(v.z, v.w);
    float rx = v.x - __low2float(h01), ry = v.y - __high2float(h01);
    float rz = v.z - __low2float(h23), rw = v.w - __high2float(h23);
    __nv_bfloat162 l01 = __floats2bfloat162_rn(rx, ry);
    __nv_bfloat162 l23 = __floats2bfloat162_rn(rz, rw);
    uh.x = *(uint32_t*)&h01; uh.y = *(uint32_t*)&h23;
    ul.x = *(uint32_t*)&l01; ul.y = *(uint32_t*)&l23;
}

// ---------------------------------------------------------------------------
// Weight pre-split (unchanged)
// ---------------------------------------------------------------------------
__global__ void wsplit_kernel(const float* __restrict__ wqkv,
                              const float* __restrict__ wproj) {
    int i = blockIdx.x * blockDim.x + threadIdx.x;
    float v; int k, nl; char *dh, *dl; size_t base;
    if (i < 49152) {
        k = i / 384; int n = i - k * 384;
        int nblk = n >> 7; nl = n & 127;
        v = wqkv[i];
        dh = g_wqh; dl = g_wql;
        base = (size_t)nblk * 32768;
    } else {
        int j = i - 49152;
        k = j >> 7; nl = j & 127;
        v = wproj[j];
        dh = g_wph; dl = g_wpl;
        base = 0;
    }
    __nv_bfloat16 h = __float2bfloat16(v);
    __nv_bfloat16 l = __float2bfloat16(v - __bfloat162float(h));
    int phase = k >> 5, kk = k & 31;
    int n4 = nl >> 2;
    int off = (((kk >> 3) << 4) | (n4 >> 1)) * 128 + (kk & 7) * 16 + (n4 & 1) * 8 + (nl & 3) * 2;
    size_t o = base + (size_t)phase * 8192 + off;
    *(uint16_t*)(dh + o) = *(uint16_t*)&h;
    *(uint16_t*)(dl + o) = *(uint16_t*)&l;
}

// ---------------------------------------------------------------------------
// cp.async issue for one GEMM K-phase (M=64 tile, 128 threads)
// ---------------------------------------------------------------------------
__device__ __forceinline__ void gemm_issue_phase(
    const float* __restrict__ A, int lda,
    const char* __restrict__ Bh, const char* __restrict__ Bl,
    uint32_t aF, uint32_t bS, int p, int tid)
{
    int buf = p & 1;
    // A: 64 rows x 32 k fp32 = 8KB = 512 x 16B
    #pragma unroll
    for (int it = 0; it < 4; it++) {
        int idx = it * 128 + tid;
        int row = idx >> 3, k4 = idx & 7;
        cp16(aF + buf * 8192 + idx * 16, A + row * lda + p * 32 + k4 * 4);
    }
    // B: hi 8KB + lo 8KB
    #pragma unroll
    for (int it = 0; it < 4; it++) {
        int idx = it * 128 + tid;
        cp16(bS + buf * 16384 + idx * 16,        Bh + p * 8192 + idx * 16);
        cp16(bS + buf * 16384 + 8192 + idx * 16, Bl + p * 8192 + idx * 16);
    }
    asm volatile("cp.async.commit_group;" ::: "memory");
}

// ---------------------------------------------------------------------------
// Split-bf16 HMMA GEMM body, M=64 x N=128, 128 threads, cp.async pipeline.
// ---------------------------------------------------------------------------
__device__ __forceinline__ void gemm_mma_body(
    const float* __restrict__ A, int lda,
    const char* __restrict__ Bh, const char* __restrict__ Bl,
    char* sm, float acc[16][4])
{
    int tid  = threadIdx.x;     // 0..127
    int lane = tid & 31;
    int wid  = tid >> 5;        // 0..3
    uint32_t sbase = smem_u32(sm);
    uint32_t aF = sbase + SM_AF32;
    uint32_t aS = sbase + SM_ASP;
    uint32_t bS = sbase + SM_B;
    int sel = lane >> 3;

    gemm_issue_phase(A, lda, Bh, Bl, aF, bS, 0, tid);
    gemm_issue_phase(A, lda, Bh, Bl, aF, bS, 1, tid);

    #pragma unroll
    for (int p = 0; p < 4; p++) {
        if (p == 3) asm volatile("cp.async.wait_group 0;" ::: "memory");
        else        asm volatile("cp.async.wait_group 1;" ::: "memory");
        __syncthreads();

        int buf = p & 1;
        // convert A fp32 (smem) -> split bf16 tiles (smem)
        #pragma unroll
        for (int it = 0; it < 4; it++) {
            int idx = it * 128 + tid;
            int row = idx >> 3, k4 = idx & 7;
            float4 v = *(const float4*)(sm + SM_AF32 + buf * 8192 + idx * 16);
            int off = (((row >> 3) << 2) | (k4 >> 1)) * 128 + (row & 7) * 16 + (k4 & 1) * 8;
            uint2 uh, ul; split4(v, uh, ul);
            *(uint2*)(sm + SM_ASP + off)        = uh;
            *(uint2*)(sm + SM_ASP + 4096 + off) = ul;
        }
        __syncthreads();

        uint32_t bBase = bS + buf * 16384;
        #pragma unroll
        for (int ks = 0; ks < 2; ks++) {
            uint32_t ah[4], al[4];
            {
                int r8 = 2 * wid + (sel & 1);      // 0..7 (64 rows)
                int k8 = 2 * ks  + (sel >> 1);
                uint32_t ad = aS + (((r8 << 2) | k8) << 7) + ((lane & 7) << 4);
                ldsm_x4(ah, ad);
                ldsm_x4(al, ad + 4096);
            }
            #pragma unroll
            for (int jp = 0; jp < 8; jp++) {
                uint32_t bh[4], bl[4];
                int k8 = 2 * ks + (sel & 1);
                int n8 = 2 * jp + (sel >> 1);
                uint32_t bd = bBase + (((k8 << 4) | n8) << 7) + ((lane & 7) << 4);
                ldsm_x4_t(bh, bd);
                ldsm_x4_t(bl, bd + 8192);
                #pragma unroll
                for (int u = 0; u < 2; u++) {
                    int t = 2 * jp + u;
                    mma16816(acc[t], ah, bh[2*u], bh[2*u+1]);
                    mma16816(acc[t], ah, bl[2*u], bl[2*u+1]);
                    mma16816(acc[t], al, bh[2*u], bh[2*u+1]);
                }
            }
        }
        __syncthreads();
        if (p < 2)
            gemm_issue_phase(A, lda, Bh, Bl, aF, bS, p + 2, tid);
    }
}

// ---------------------------------------------------------------------------
// QKV GEMM + fused KV-cache copy. blockIdx.y: 0:q 1:k 2:v 3:copy_past
// Grid: (512, 4) x 128 threads.
// ---------------------------------------------------------------------------
__global__ __launch_bounds__(128, 4) void qkv_mma_kernel(
    const float* __restrict__ x,
    const float4* __restrict__ pk, const float4* __restrict__ pv,
    float* __restrict__ outk, float* __restrict__ outv)
{
    extern __shared__ char sm[];
    int mode = blockIdx.y;
    int tid = threadIdx.x;

    if (mode == 3) {
        float4* ok = (float4*)outk;
        float4* ov = (float4*)outv;
        int base = blockIdx.x * 128 + tid;       // 65536 threads total
        #pragma unroll
        for (int it = 0; it < 16; it++) {
            int i = base + it * 65536;
            int r   = i & 7;
            int row = i >> 3;
            int t   = row & 255;
            int bh  = row >> 8;
            int dst = (bh * TFULL + t) * 8 + r;
            ok[dst] = pk[i];
            ov[dst] = pv[i];
        }
        return;
    }

    int m0 = blockIdx.x * 64;

    float acc[16][4];
    #pragma unroll
    for (int t = 0; t < 16; t++)
        #pragma unroll
        for (int j = 0; j < 4; j++) acc[t][j] = 0.f;

    gemm_mma_body(x + (size_t)m0 * 128, 128, g_wqh + (size_t)mode * 32768,
                  g_wql + (size_t)mode * 32768, sm, acc);

    int lane = tid & 31, wid = tid >> 5;
    int g = lane >> 2, c = lane & 3;
    #pragma unroll
    for (int t = 0; t < 16; t++) {
        int n = t * 8 + c * 2;
        int h = n >> 5, d = n & 31;
        #pragma unroll
        for (int rr = 0; rr < 2; rr++) {
            int m = m0 + wid * 16 + g + rr * 8;
            int b_ = m >> 8, t_ = m & 255;
            float2 v = rr ? make_float2(acc[t][2], acc[t][3])
                          : make_float2(acc[t][0], acc[t][1]);
            float* dst;
            if (mode == 0)      dst = &g_q [((b_ * NH + h) * TT + t_) * DH + d];
            else if (mode == 1) dst = &outk[((b_ * NH + h) * TFULL + TPAST + t_) * DH + d];
            else                dst = &outv[((b_ * NH + h) * TFULL + TPAST + t_) * DH + d];
            *(float2*)dst = v;
        }
    }
}

__global__ __launch_bounds__(128, 4) void proj_mma_kernel(float* __restrict__ out)
{
    extern __shared__ char sm[];
    int m0 = blockIdx.x * 64;

    float acc[16][4];
    #pragma unroll
    for (int t = 0; t < 16; t++)
        #pragma unroll
        for (int j = 0; j < 4; j++) acc[t][j] = 0.f;

    gemm_mma_body(g_ao + (size_t)m0 * 128, 128, g_wph, g_wpl, sm, acc);

    int lane = threadIdx.x & 31, wid = threadIdx.x >> 5;
    int g = lane >> 2, c = lane & 3;
    #pragma unroll
    for (int t = 0; t < 16; t++) {
        int n = t * 8 + c * 2;
        #pragma unroll
        for (int rr = 0; rr < 2; rr++) {
            int m = m0 + wid * 16 + g + rr * 8;
            float2 v = rr ? make_float2(acc[t][2], acc[t][3])
                          : make_float2(acc[t][0], acc[t][1]);
            *(float2*)&out[(size_t)m * 128 + n] = v;
        }
    }
}

// ---------------------------------------------------------------------------
// Flash-style HMMA attention (unchanged from R14 best).
// ---------------------------------------------------------------------------
#define PITCH 40

__global__ __launch_bounds__(256, 2) void attn_mma_kernel(
    const float* __restrict__ kf, const float* __restrict__ vf)
{
    __shared__ __align__(16) uint16_t sKh[128 * PITCH];
    __shared__ __align__(16) uint16_t sKl[128 * PITCH];
    __shared__ __align__(16) uint16_t sV [128 * PITCH];

    int tid  = threadIdx.x;
    int lane = tid & 31;
    int w    = tid >> 5;
    int bh   = blockIdx.x >> 1;
    int half = blockIdx.x & 1;
    int qbase = half * 128;

    uint32_t khB = smem_u32(sKh);
    uint32_t klB = smem_u32(sKl);
    uint32_t vB  = smem_u32(sV);

    const float QSC = 0.17677669529663687f * 1.4426950408889634f; // scale*log2e

    {
        const float* qsrc = g_q + (size_t)(bh * TT + qbase) * DH;
        #pragma unroll
        for (int it = 0; it < 4; it++) {
            int idx = it * 256 + tid;
            int row = idx >> 3, c4 = idx & 7;
            float4 v = *(const float4*)&qsrc[row * 32 + c4 * 4];
            v.x *= QSC; v.y *= QSC; v.z *= QSC; v.w *= QSC;
            uint2 uh, ul; split4(v, uh, ul);
            int off = row * PITCH + c4 * 4;
            *(uint2*)((char*)sKh + off * 2) = uh;
            *(uint2*)((char*)sKl + off * 2) = ul;
        }
    }
    __syncthreads();

    uint32_t qh[2][4], ql[2][4];
    int mat = lane >> 3;
    {
        int qrow = w * 16 + (mat & 1) * 8 + (lane & 7);
        #pragma unroll
        for (int ks = 0; ks < 2; ks++) {
            uint32_t off = (uint32_t)(qrow * PITCH + ks * 16 + (mat >> 1) * 8) * 2;
            ldsm_x4(qh[ks], khB + off);
            ldsm_x4(ql[ks], klB + off);
        }
    }

    float oacc[4][4];
    #pragma unroll
    for (int t = 0; t < 4; t++)
        #pragma unroll
        for (int j = 0; j < 4; j++) oacc[t][j] = 0.f;
    float l0 = 0.f, l1 = 0.f;

    int nchunks = 3 + half;
    int klim0 = TPAST + qbase + w * 16 + (lane >> 2);

    for (int c = 0; c < nchunks; c++) {
        __syncthreads();
        {
            const float* ksrc = kf + (size_t)(bh * TFULL + c * 128) * 32;
            const float* vsrc = vf + (size_t)(bh * TFULL + c * 128) * 32;
            #pragma unroll
            for (int it = 0; it < 4; it++) {
                int idx = it * 256 + tid;
                int row = idx >> 3, c4 = idx & 7;
                int off = row * PITCH + c4 * 4;
                float4 kv = *(const float4*)&ksrc[row * 32 + c4 * 4];
                uint2 uh, ul; split4(kv, uh, ul);
                *(uint2*)((char*)sKh + off * 2) = uh;
                *(uint2*)((char*)sKl + off * 2) = ul;
                float4 vv = *(const float4*)&vsrc[row * 32 + c4 * 4];
                __half2 v01 = __floats2half2_rn(vv.x, vv.y);
                __half2 v23 = __floats2half2_rn(vv.z, vv.w);
                uint2 uv; uv.x = *(uint32_t*)&v01; uv.y = *(uint32_t*)&v23;
                *(uint2*)((char*)sV + off * 2) = uv;
            }
        }
        __syncthreads();

        float sacc[16][4];
        #pragma unroll
        for (int t = 0; t < 16; t++)
            #pragma unroll
            for (int j = 0; j < 4; j++) sacc[t][j] = 0.f;

        #pragma unroll
        for (int ks = 0; ks < 2; ks++) {
            #pragma unroll
            for (int kg = 0; kg < 8; kg++) {
                int key = kg * 16 + (mat >> 1) * 8 + (lane & 7);
                uint32_t off = (uint32_t)(key * PITCH + ks * 16 + (mat & 1) * 8) * 2;
                uint32_t bhh[4], bll[4];
                ldsm_x4(bhh, khB + off);
                ldsm_x4(bll, klB + off);
                #pragma unroll
                for (int u = 0; u < 2; u++) {
                    int t = 2 * kg + u;
                    mma16816(sacc[t], qh[ks], bhh[2*u], bhh[2*u+1]);
                    mma16816(sacc[t], qh[ks], bll[2*u], bll[2*u+1]);
                    mma16816(sacc[t], ql[ks], bhh[2*u], bhh[2*u+1]);
                }
            }
        }

        bool masked = (c == 2 + half);
        #pragma unroll
        for (int t2 = 0; t2 < 8; t2++) {
            uint32_t pa[4];
            #pragma unroll
            for (int u = 0; u < 2; u++) {
                int t = 2 * t2 + u;
                float p0, p1, p2, p3;
                if (masked) {
                    int kcol = c * 128 + t * 8 + (lane & 3) * 2;
                    p0 = (kcol     <= klim0)     ? exp2f(fminf(sacc[t][0], 80.f)) : 0.f;
                    p1 = (kcol + 1 <= klim0)     ? exp2f(fminf(sacc[t][1], 80.f)) : 0.f;
                    p2 = (kcol     <= klim0 + 8) ? exp2f(fminf(sacc[t][2], 80.f)) : 0.f;
                    p3 = (kcol + 1 <= klim0 + 8) ? exp2f(fminf(sacc[t][3], 80.f)) : 0.f;
                } else {
                    p0 = exp2f(fminf(sacc[t][0], 80.f));
                    p1 = exp2f(fminf(sacc[t][1], 80.f));
                    p2 = exp2f(fminf(sacc[t][2], 80.f));
                    p3 = exp2f(fminf(sacc[t][3], 80.f));
                }
                l0 += p0 + p1;
                l1 += p2 + p3;
                __half2 h01 = __floats2half2_rn(p0, p1);
                __half2 h23 = __floats2half2_rn(p2, p3);
                pa[2*u]   = *(uint32_t*)&h01;
                pa[2*u+1] = *(uint32_t*)&h23;
            }
            #pragma unroll
            for (int vh = 0; vh < 2; vh++) {
                int key = t2 * 16 + (mat & 1) * 8 + (lane & 7);
                uint32_t off = (uint32_t)(key * PITCH + vh * 16 + (mat >> 1) * 8) * 2;
                uint32_t vb[4];
                ldsm_x4_t(vb, vB + off);
                mma16816_f16(oacc[2*vh],   pa, vb[0], vb[1]);
                mma16816_f16(oacc[2*vh+1], pa, vb[2], vb[3]);
            }
        }
    }

    l0 += __shfl_xor_sync(0xffffffff, l0, 1);
    l0 += __shfl_xor_sync(0xffffffff, l0, 2);
    l1 += __shfl_xor_sync(0xffffffff, l1, 1);
    l1 += __shfl_xor_sync(0xffffffff, l1, 2);
    float inv0 = 1.f / l0, inv1 = 1.f / l1;

    int b_ = bh >> 2, h = bh & 3;
    int q0 = qbase + w * 16 + (lane >> 2);
    float* out0 = &g_ao[(size_t)(b_ * TT + q0)     * DM + h * DH];
    float* out1 = &g_ao[(size_t)(b_ * TT + q0 + 8) * DM + h * DH];
    #pragma unroll
    for (int t = 0; t < 4; t++) {
        int d = t * 8 + (lane & 3) * 2;
        *(float2*)&out0[d] = make_float2(oacc[t][0] * inv0, oacc[t][1] * inv0);
        *(float2*)&out1[d] = make_float2(oacc[t][2] * inv1, oacc[t][3] * inv1);
    }
}

// ---------------------------------------------------------------------------
extern "C" void kernel_launch(void* const* d_in, const int* in_sizes, int n_in,
                              void* d_out, int out_size) {
    const float* x     = (const float*)d_in[0];
    const float* pk    = (const float*)d_in[1];
    const float* pv    = (const float*)d_in[2];
    const float* wqkv  = (const float*)d_in[3];
    const float* wproj = (const float*)d_in[4];
    float* out  = (float*)d_out;
    float* outk = out + OUT_K_OFF;
    float* outv = out + OUT_V_OFF;

    cudaFuncSetAttribute(qkv_mma_kernel,
                         cudaFuncAttributeMaxDynamicSharedMemorySize, GEMM_SMEM);
    cudaFuncSetAttribute(proj_mma_kernel,
                         cudaFuncAttributeMaxDynamicSharedMemorySize, GEMM_SMEM);

    wsplit_kernel<<<256, 256>>>(wqkv, wproj);
    qkv_mma_kernel<<<dim3(512, 4), 128, GEMM_SMEM>>>(
        x, (const float4*)pk, (const float4*)pv, outk, outv);
    attn_mma_kernel<<<1024, 256>>>(outk, outv);
    proj_mma_kernel<<<512, 128, GEMM_SMEM>>>(out);
}

// round 16
// speedup vs baseline: 1.0628x; 1.0628x over previous
#include <cuda_runtime.h>
#include <cuda_bf16.h>
#include <cuda_fp16.h>
#include <cstdint>

#define BB 128
#define TT 256
#define TPAST 256
#define TFULL 512
#define NH 4
#define DH 32
#define DM 128

#define OUT_K_OFF  4194304
#define OUT_V_OFF 12582912

__device__ float g_q [BB*NH*TT*DH];   // (B,H,T,Dh)
__device__ float g_ao[BB*TT*DM];      // (B,T,D) pre-proj

// Pre-split weights in GEMM-B smem layout: [mode][phase(4)][8KB]
__device__ char g_wqh[3 * 32768];
__device__ char g_wql[3 * 32768];
__device__ char g_wph[32768];
__device__ char g_wpl[32768];

// proj GEMM smem layout (R14/R12 proven)
#define SM_AF32 0          // 2 x 16KB fp32 A staging (double buffer)
#define SM_ASP  32768      // 16KB split A tiles (hi 8K + lo 8K)
#define SM_B    49152      // 2 x 16KB split B (double buffer)
#define GEMM_SMEM 81920

// fused qkv smem layout: A split for ALL K (hi 32KB + lo 32KB) + B double buf
#define QA_H 0
#define QA_L 32768
#define QB   65536
#define QKV_SMEM 98304

// ---- baseline tensor-core helpers (sm_80+ features; OK for sm_103) ---------
__device__ __forceinline__ uint32_t smem_u32(const void* p) {
    uint32_t a;
    asm("{ .reg .u64 t; cvta.to.shared.u64 t, %1; cvt.u32.u64 %0, t; }" : "=r"(a) : "l"(p));
    return a;
}
__device__ __forceinline__ void ldsm_x4(uint32_t r[4], uint32_t addr) {
    asm volatile("ldmatrix.sync.aligned.m8n8.x4.shared.b16 {%0,%1,%2,%3}, [%4];"
        : "=r"(r[0]), "=r"(r[1]), "=r"(r[2]), "=r"(r[3]) : "r"(addr));
}
__device__ __forceinline__ void ldsm_x4_t(uint32_t r[4], uint32_t addr) {
    asm volatile("ldmatrix.sync.aligned.m8n8.x4.trans.shared.b16 {%0,%1,%2,%3}, [%4];"
        : "=r"(r[0]), "=r"(r[1]), "=r"(r[2]), "=r"(r[3]) : "r"(addr));
}
__device__ __forceinline__ void mma16816(float c[4], const uint32_t a[4],
                                         uint32_t b0, uint32_t b1) {
    asm volatile(
        "mma.sync.aligned.m16n8k16.row.col.f32.bf16.bf16.f32 "
        "{%0,%1,%2,%3}, {%4,%5,%6,%7}, {%8,%9}, {%0,%1,%2,%3};"
        : "+f"(c[0]), "+f"(c[1]), "+f"(c[2]), "+f"(c[3])
        : "r"(a[0]), "r"(a[1]), "r"(a[2]), "r"(a[3]), "r"(b0), "r"(b1));
}
__device__ __forceinline__ void mma16816_f16(float c[4], const uint32_t a[4],
                                             uint32_t b0, uint32_t b1) {
    asm volatile(
        "mma.sync.aligned.m16n8k16.row.col.f32.f16.f16.f32 "
        "{%0,%1,%2,%3}, {%4,%5,%6,%7}, {%8,%9}, {%0,%1,%2,%3};"
        : "+f"(c[0]), "+f"(c[1]), "+f"(c[2]), "+f"(c[3])
        : "r"(a[0]), "r"(a[1]), "r"(a[2]), "r"(a[3]), "r"(b0), "r"(b1));
}
__device__ __forceinline__ void cp16(uint32_t saddr, const void* g) {
    asm volatile("cp.async.cg.shared.global [%0], [%1], 16;"
                 :: "r"(saddr), "l"(g) : "memory");
}

// Split a float4 into hi/lo bf16x4 (8B each)
__device__ __forceinline__ void split4(const float4& v, uint2& uh, uint2& ul) {
    __nv_bfloat162 h01 = __floats2bfloat162_rn(v.x, v.y);
    __nv_bfloat162 h23 = __floats2bfloat162_rn(v.z, v.w);
    float rx = v.x - __low2float(h01), ry = v.y - __high2float(h01);
    float rz = v.z - __low2float(h23), rw = v.w - __high2float(h23);
    __nv_bfloat162 l01 = __floats2bfloat162_rn(rx, ry);
    __nv_bfloat162 l23 = __floats2bfloat162_rn(rz, rw);
    uh.x = *(uint32_t*)&h01; uh.y = *(uint32_t*)&h23;
    ul.x = *(uint32_t*)&l01; ul.y = *(uint32_t*)&l23;
}

// ---------------------------------------------------------------------------
// Weight pre-split (unchanged)
// ---------------------------------------------------------------------------
__global__ void wsplit_kernel(const float* __restrict__ wqkv,
                              const float* __restrict__ wproj) {
    int i = blockIdx.x * blockDim.x + threadIdx.x;
    float v; int k, nl; char *dh, *dl; size_t base;
    if (i < 49152) {
        k = i / 384; int n = i - k * 384;
        int nblk = n >> 7; nl = n & 127;
        v = wqkv[i];
        dh = g_wqh; dl = g_wql;
        base = (size_t)nblk * 32768;
    } else {
        int j = i - 49152;
        k = j >> 7; nl = j & 127;
        v = wproj[j];
        dh = g_wph; dl = g_wpl;
        base = 0;
    }
    __nv_bfloat16 h = __float2bfloat16(v);
    __nv_bfloat16 l = __float2bfloat16(v - __bfloat162float(h));
    int phase = k >> 5, kk = k & 31;
    int n4 = nl >> 2;
    int off = (((kk >> 3) << 4) | (n4 >> 1)) * 128 + (kk & 7) * 16 + (n4 & 1) * 8 + (nl & 3) * 2;
    size_t o = base + (size_t)phase * 8192 + off;
    *(uint16_t*)(dh + o) = *(uint16_t*)&h;
    *(uint16_t*)(dl + o) = *(uint16_t*)&l;
}

// ---------------------------------------------------------------------------
// GEMM MMA phase compute (A hi/lo at aHi / aHi+aLoOff, B hi/lo in 16KB tile)
// ---------------------------------------------------------------------------
__device__ __forceinline__ void gemm_phase_mma(uint32_t aHi, uint32_t aLoOff,
                                               uint32_t bBase,
                                               int lane, int wid, int sel,
                                               float acc[16][4]) {
    #pragma unroll
    for (int ks = 0; ks < 2; ks++) {
        uint32_t ah[4], al[4];
        {
            int r8 = 2 * wid + (sel & 1);
            int k8 = 2 * ks  + (sel >> 1);
            uint32_t ad = aHi + (((r8 << 2) | k8) << 7) + ((lane & 7) << 4);
            ldsm_x4(ah, ad);
            ldsm_x4(al, ad + aLoOff);
        }
        #pragma unroll
        for (int jp = 0; jp < 8; jp++) {
            uint32_t bh[4], bl[4];
            int k8 = 2 * ks + (sel & 1);
            int n8 = 2 * jp + (sel >> 1);
            uint32_t bd = bBase + (((k8 << 4) | n8) << 7) + ((lane & 7) << 4);
            ldsm_x4_t(bh, bd);
            ldsm_x4_t(bl, bd + 8192);
            #pragma unroll
            for (int u = 0; u < 2; u++) {
                int t = 2 * jp + u;
                mma16816(acc[t], ah, bh[2*u], bh[2*u+1]);
                mma16816(acc[t], ah, bl[2*u], bl[2*u+1]);
                mma16816(acc[t], al, bh[2*u], bh[2*u+1]);
            }
        }
    }
}

// ---------------------------------------------------------------------------
// Fused QKV: one CTA computes all 3 modes for a 128-row stripe.
// A loaded+split ONCE (full K in smem); B cp.async double-buffered over
// 12 (mode,phase) iterations. blockIdx.y: 0 = gemm, 1 = copy_past.
// ---------------------------------------------------------------------------
__global__ __launch_bounds__(256, 2) void qkv_mma_kernel(
    const float* __restrict__ x,
    const float4* __restrict__ pk, const float4* __restrict__ pv,
    float* __restrict__ outk, float* __restrict__ outv)
{
    extern __shared__ char sm[];
    int tid = threadIdx.x;

    if (blockIdx.y == 1) {
        float4* ok = (float4*)outk;
        float4* ov = (float4*)outv;
        int base = blockIdx.x * 256 + tid;
        #pragma unroll
        for (int it = 0; it < 16; it++) {
            int i = base + it * 65536;
            int r   = i & 7;
            int row = i >> 3;
            int t   = row & 255;
            int bh  = row >> 8;
            int dst = (bh * TFULL + t) * 8 + r;
            ok[dst] = pk[i];
            ov[dst] = pv[i];
        }
        return;
    }

    int m0 = blockIdx.x * 128;
    int lane = tid & 31, wid = tid >> 5;
    int sel = lane >> 3;
    uint32_t sbase = smem_u32(sm);
    uint32_t bS = sbase + QB;

    // issue B for (mode0,p0) and (mode0,p1)
    #pragma unroll
    for (int g0 = 0; g0 < 2; g0++) {
        const char* Bh = g_wqh + g0 * 8192;
        const char* Bl = g_wql + g0 * 8192;
        #pragma unroll
        for (int it = 0; it < 2; it++) {
            int idx = it * 256 + tid;
            cp16(bS + g0 * 16384 + idx * 16,        Bh + idx * 16);
            cp16(bS + g0 * 16384 + 8192 + idx * 16, Bl + idx * 16);
        }
        asm volatile("cp.async.commit_group;" ::: "memory");
    }

    // load + split A ONCE for all K (128 x 128 fp32 -> hi/lo tiles per phase)
    {
        const float* A = x + (size_t)m0 * 128;
        #pragma unroll
        for (int it = 0; it < 16; it++) {
            int idx = it * 256 + tid;         // 4096 float4
            int row = idx >> 5, c4 = idx & 31;
            float4 v = *(const float4*)&A[row * 128 + c4 * 4];
            int phase = c4 >> 3, k4p = c4 & 7;
            int off = (((row >> 3) << 2) | (k4p >> 1)) * 128 + (row & 7) * 16 + (k4p & 1) * 8;
            uint2 uh, ul; split4(v, uh, ul);
            *(uint2*)(sm + QA_H + phase * 8192 + off) = uh;
            *(uint2*)(sm + QA_L + phase * 8192 + off) = ul;
        }
    }

    float acc[16][4];
    int g = lane >> 2, c = lane & 3;

    #pragma unroll
    for (int mode = 0; mode < 3; mode++) {
        #pragma unroll
        for (int t = 0; t < 16; t++)
            #pragma unroll
            for (int j = 0; j < 4; j++) acc[t][j] = 0.f;

        #pragma unroll
        for (int p = 0; p < 4; p++) {
            int itg = mode * 4 + p;
            if (itg == 11) asm volatile("cp.async.wait_group 0;" ::: "memory");
            else           asm volatile("cp.async.wait_group 1;" ::: "memory");
            __syncthreads();   // B[buf] ready (and A tiles on first pass)

            gemm_phase_mma(sbase + QA_H + p * 8192, 32768,
                           bS + (itg & 1) * 16384, lane, wid, sel, acc);
            __syncthreads();   // B[buf] consumed

            if (itg < 10) {
                int nxt = itg + 2;
                const char* Bh = g_wqh + (nxt >> 2) * 32768 + (nxt & 3) * 8192;
                const char* Bl = g_wql + (nxt >> 2) * 32768 + (nxt & 3) * 8192;
                #pragma unroll
                for (int it = 0; it < 2; it++) {
                    int idx = it * 256 + tid;
                    cp16(bS + (nxt & 1) * 16384 + idx * 16,        Bh + idx * 16);
                    cp16(bS + (nxt & 1) * 16384 + 8192 + idx * 16, Bl + idx * 16);
                }
            }
            asm volatile("cp.async.commit_group;" ::: "memory");
        }

        // epilogue for this mode
        #pragma unroll
        for (int t = 0; t < 16; t++) {
            int n = t * 8 + c * 2;
            int h = n >> 5, d = n & 31;
            #pragma unroll
            for (int rr = 0; rr < 2; rr++) {
                int m = m0 + wid * 16 + g + rr * 8;
                int b_ = m >> 8, t_ = m & 255;
                float2 v = rr ? make_float2(acc[t][2], acc[t][3])
                              : make_float2(acc[t][0], acc[t][1]);
                float* dst;
                if (mode == 0)      dst = &g_q [((b_ * NH + h) * TT + t_) * DH + d];
                else if (mode == 1) dst = &outk[((b_ * NH + h) * TFULL + TPAST + t_) * DH + d];
                else                dst = &outv[((b_ * NH + h) * TFULL + TPAST + t_) * DH + d];
                *(float2*)dst = v;
            }
        }
    }
}

// ---------------------------------------------------------------------------
// Proj GEMM (exact R14/R12 version: M=128, 256 threads, cp.async pipeline)
// ---------------------------------------------------------------------------
__device__ __forceinline__ void proj_issue_phase(
    const float* __restrict__ A,
    uint32_t aF, uint32_t bS, int p, int tid)
{
    int buf = p & 1;
    #pragma unroll
    for (int it = 0; it < 4; it++) {
        int idx = it * 256 + tid;
        int row = idx >> 3, k4 = idx & 7;
        cp16(aF + buf * 16384 + idx * 16, A + row * 128 + p * 32 + k4 * 4);
    }
    #pragma unroll
    for (int it = 0; it < 2; it++) {
        int idx = it * 256 + tid;
        cp16(bS + buf * 16384 + idx * 16,        g_wph + p * 8192 + idx * 16);
        cp16(bS + buf * 16384 + 8192 + idx * 16, g_wpl + p * 8192 + idx * 16);
    }
    asm volatile("cp.async.commit_group;" ::: "memory");
}

__global__ __launch_bounds__(256, 2) void proj_mma_kernel(float* __restrict__ out)
{
    extern __shared__ char sm[];
    int tid  = threadIdx.x;
    int lane = tid & 31;
    int wid  = tid >> 5;
    int m0 = blockIdx.x * 128;
    uint32_t sbase = smem_u32(sm);
    uint32_t aF = sbase + SM_AF32;
    uint32_t aS = sbase + SM_ASP;
    uint32_t bS = sbase + SM_B;
    int sel = lane >> 3;
    const float* A = g_ao + (size_t)m0 * 128;

    float acc[16][4];
    #pragma unroll
    for (int t = 0; t < 16; t++)
        #pragma unroll
        for (int j = 0; j < 4; j++) acc[t][j] = 0.f;

    proj_issue_phase(A, aF, bS, 0, tid);
    proj_issue_phase(A, aF, bS, 1, tid);

    #pragma unroll
    for (int p = 0; p < 4; p++) {
        if (p == 3) asm volatile("cp.async.wait_group 0;" ::: "memory");
        else        asm volatile("cp.async.wait_group 1;" ::: "memory");
        __syncthreads();

        int buf = p & 1;
        #pragma unroll
        for (int it = 0; it < 4; it++) {
            int idx = it * 256 + tid;
            int row = idx >> 3, k4 = idx & 7;
            float4 v = *(const float4*)(sm + SM_AF32 + buf * 16384 + idx * 16);
            int off = (((row >> 3) << 2) | (k4 >> 1)) * 128 + (row & 7) * 16 + (k4 & 1) * 8;
            uint2 uh, ul; split4(v, uh, ul);
            *(uint2*)(sm + SM_ASP + off)        = uh;
            *(uint2*)(sm + SM_ASP + 8192 + off) = ul;
        }
        __syncthreads();

        gemm_phase_mma(aS, 8192, bS + buf * 16384, lane, wid, sel, acc);
        __syncthreads();
        if (p < 2)
            proj_issue_phase(A, aF, bS, p + 2, tid);
    }

    int g = lane >> 2, c = lane & 3;
    #pragma unroll
    for (int t = 0; t < 16; t++) {
        int n = t * 8 + c * 2;
        #pragma unroll
        for (int rr = 0; rr < 2; rr++) {
            int m = m0 + wid * 16 + g + rr * 8;
            float2 v = rr ? make_float2(acc[t][2], acc[t][3])
                          : make_float2(acc[t][0], acc[t][1]);
            *(float2*)&out[(size_t)m * 128 + n] = v;
        }
    }
}

// ---------------------------------------------------------------------------
// Flash-style HMMA attention (unchanged from R14 best).
// ---------------------------------------------------------------------------
#define PITCH 40

__global__ __launch_bounds__(256, 2) void attn_mma_kernel(
    const float* __restrict__ kf, const float* __restrict__ vf)
{
    __shared__ __align__(16) uint16_t sKh[128 * PITCH];
    __shared__ __align__(16) uint16_t sKl[128 * PITCH];
    __shared__ __align__(16) uint16_t sV [128 * PITCH];

    int tid  = threadIdx.x;
    int lane = tid & 31;
    int w    = tid >> 5;
    int bh   = blockIdx.x >> 1;
    int half = blockIdx.x & 1;
    int qbase = half * 128;

    uint32_t khB = smem_u32(sKh);
    uint32_t klB = smem_u32(sKl);
    uint32_t vB  = smem_u32(sV);

    const float QSC = 0.17677669529663687f * 1.4426950408889634f; // scale*log2e

    {
        const float* qsrc = g_q + (size_t)(bh * TT + qbase) * DH;
        #pragma unroll
        for (int it = 0; it < 4; it++) {
            int idx = it * 256 + tid;
            int row = idx >> 3, c4 = idx & 7;
            float4 v = *(const float4*)&qsrc[row * 32 + c4 * 4];
            v.x *= QSC; v.y *= QSC; v.z *= QSC; v.w *= QSC;
            uint2 uh, ul; split4(v, uh, ul);
            int off = row * PITCH + c4 * 4;
            *(uint2*)((char*)sKh + off * 2) = uh;
            *(uint2*)((char*)sKl + off * 2) = ul;
        }
    }
    __syncthreads();

    uint32_t qh[2][4], ql[2][4];
    int mat = lane >> 3;
    {
        int qrow = w * 16 + (mat & 1) * 8 + (lane & 7);
        #pragma unroll
        for (int ks = 0; ks < 2; ks++) {
            uint32_t off = (uint32_t)(qrow * PITCH + ks * 16 + (mat >> 1) * 8) * 2;
            ldsm_x4(qh[ks], khB + off);
            ldsm_x4(ql[ks], klB + off);
        }
    }

    float oacc[4][4];
    #pragma unroll
    for (int t = 0; t < 4; t++)
        #pragma unroll
        for (int j = 0; j < 4; j++) oacc[t][j] = 0.f;
    float l0 = 0.f, l1 = 0.f;

    int nchunks = 3 + half;
    int klim0 = TPAST + qbase + w * 16 + (lane >> 2);

    for (int c = 0; c < nchunks; c++) {
        __syncthreads();
        {
            const float* ksrc = kf + (size_t)(bh * TFULL + c * 128) * 32;
            const float* vsrc = vf + (size_t)(bh * TFULL + c * 128) * 32;
            #pragma unroll
            for (int it = 0; it < 4; it++) {
                int idx = it * 256 + tid;
                int row = idx >> 3, c4 = idx & 7;
                int off = row * PITCH + c4 * 4;
                float4 kv = *(const float4*)&ksrc[row * 32 + c4 * 4];
                uint2 uh, ul; split4(kv, uh, ul);
                *(uint2*)((char*)sKh + off * 2) = uh;
                *(uint2*)((char*)sKl + off * 2) = ul;
                float4 vv = *(const float4*)&vsrc[row * 32 + c4 * 4];
                __half2 v01 = __floats2half2_rn(vv.x, vv.y);
                __half2 v23 = __floats2half2_rn(vv.z, vv.w);
                uint2 uv; uv.x = *(uint32_t*)&v01; uv.y = *(uint32_t*)&v23;
                *(uint2*)((char*)sV + off * 2) = uv;
            }
        }
        __syncthreads();

        float sacc[16][4];
        #pragma unroll
        for (int t = 0; t < 16; t++)
            #pragma unroll
            for (int j = 0; j < 4; j++) sacc[t][j] = 0.f;

        #pragma unroll
        for (int ks = 0; ks < 2; ks++) {
            #pragma unroll
            for (int kg = 0; kg < 8; kg++) {
                int key = kg * 16 + (mat >> 1) * 8 + (lane & 7);
                uint32_t off = (uint32_t)(key * PITCH + ks * 16 + (mat & 1) * 8) * 2;
                uint32_t bhh[4], bll[4];
                ldsm_x4(bhh, khB + off);
                ldsm_x4(bll, klB + off);
                #pragma unroll
                for (int u = 0; u < 2; u++) {
                    int t = 2 * kg + u;
                    mma16816(sacc[t], qh[ks], bhh[2*u], bhh[2*u+1]);
                    mma16816(sacc[t], qh[ks], bll[2*u], bll[2*u+1]);
                    mma16816(sacc[t], ql[ks], bhh[2*u], bhh[2*u+1]);
                }
            }
        }

        bool masked = (c == 2 + half);
        #pragma unroll
        for (int t2 = 0; t2 < 8; t2++) {
            uint32_t pa[4];
            #pragma unroll
            for (int u = 0; u < 2; u++) {
                int t = 2 * t2 + u;
                float p0, p1, p2, p3;
                if (masked) {
                    int kcol = c * 128 + t * 8 + (lane & 3) * 2;
                    p0 = (kcol     <= klim0)     ? exp2f(fminf(sacc[t][0], 80.f)) : 0.f;
                    p1 = (kcol + 1 <= klim0)     ? exp2f(fminf(sacc[t][1], 80.f)) : 0.f;
                    p2 = (kcol     <= klim0 + 8) ? exp2f(fminf(sacc[t][2], 80.f)) : 0.f;
                    p3 = (kcol + 1 <= klim0 + 8) ? exp2f(fminf(sacc[t][3], 80.f)) : 0.f;
                } else {
                    p0 = exp2f(fminf(sacc[t][0], 80.f));
                    p1 = exp2f(fminf(sacc[t][1], 80.f));
                    p2 = exp2f(fminf(sacc[t][2], 80.f));
                    p3 = exp2f(fminf(sacc[t][3], 80.f));
                }
                l0 += p0 + p1;
                l1 += p2 + p3;
                __half2 h01 = __floats2half2_rn(p0, p1);
                __half2 h23 = __floats2half2_rn(p2, p3);
                pa[2*u]   = *(uint32_t*)&h01;
                pa[2*u+1] = *(uint32_t*)&h23;
            }
            #pragma unroll
            for (int vh = 0; vh < 2; vh++) {
                int key = t2 * 16 + (mat & 1) * 8 + (lane & 7);
                uint32_t off = (uint32_t)(key * PITCH + vh * 16 + (mat >> 1) * 8) * 2;
                uint32_t vb[4];
                ldsm_x4_t(vb, vB + off);
                mma16816_f16(oacc[2*vh],   pa, vb[0], vb[1]);
                mma16816_f16(oacc[2*vh+1], pa, vb[2], vb[3]);
            }
        }
    }

    l0 += __shfl_xor_sync(0xffffffff, l0, 1);
    l0 += __shfl_xor_sync(0xffffffff, l0, 2);
    l1 += __shfl_xor_sync(0xffffffff, l1, 1);
    l1 += __shfl_xor_sync(0xffffffff, l1, 2);
    float inv0 = 1.f / l0, inv1 = 1.f / l1;

    int b_ = bh >> 2, h = bh & 3;
    int q0 = qbase + w * 16 + (lane >> 2);
    float* out0 = &g_ao[(size_t)(b_ * TT + q0)     * DM + h * DH];
    float* out1 = &g_ao[(size_t)(b_ * TT + q0 + 8) * DM + h * DH];
    #pragma unroll
    for (int t = 0; t < 4; t++) {
        int d = t * 8 + (lane & 3) * 2;
        *(float2*)&out0[d] = make_float2(oacc[t][0] * inv0, oacc[t][1] * inv0);
        *(float2*)&out1[d] = make_float2(oacc[t][2] * inv1, oacc[t][3] * inv1);
    }
}

// ---------------------------------------------------------------------------
extern "C" void kernel_launch(void* const* d_in, const int* in_sizes, int n_in,
                              void* d_out, int out_size) {
    const float* x     = (const float*)d_in[0];
    const float* pk    = (const float*)d_in[1];
    const float* pv    = (const float*)d_in[2];
    const float* wqkv  = (const float*)d_in[3];
    const float* wproj = (const float*)d_in[4];
    float* out  = (float*)d_out;
    float* outk = out + OUT_K_OFF;
    float* outv = out + OUT_V_OFF;

    cudaFuncSetAttribute(qkv_mma_kernel,
                         cudaFuncAttributeMaxDynamicSharedMemorySize, QKV_SMEM);
    cudaFuncSetAttribute(proj_mma_kernel,
                         cudaFuncAttributeMaxDynamicSharedMemorySize, GEMM_SMEM);

    wsplit_kernel<<<256, 256>>>(wqkv, wproj);
    qkv_mma_kernel<<<dim3(256, 2), 256, QKV_SMEM>>>(
        x, (const float4*)pk, (const float4*)pv, outk, outv);
    attn_mma_kernel<<<1024, 256>>>(outk, outv);
    proj_mma_kernel<<<256, 256, GEMM_SMEM>>>(out);
}